// round 5
// baseline (speedup 1.0000x reference)
#include <cuda_runtime.h>
#include <cuda_bf16.h>

// Distance_74406013436418: trilinear SDF interpolation + finite-difference
// normals + hinge loss.
//
// Output (float32): [dss B*N | nss B*N*3 | loss 1]
//
// R4: single-kernel graph (no memset node): threadfence-reduction with a
// self-resetting ticket counter; 2 points/thread for 16-deep gather MLP.

#define EPS 1e-5f
#define TPB 256
#define PPT 2   // points per thread

// scratch for per-block loss partials (fully overwritten each launch -> deterministic)
__device__ float g_partials[8192];
// ticket counter: atomicInc with limit gridDim-1 wraps to 0 -> self-resetting across replays
__device__ unsigned int g_count = 0;

__global__ __launch_bounds__(TPB)
void sdf_trilinear_kernel(const float* __restrict__ pss,
                          const float* __restrict__ grid,
                          const float* __restrict__ first,
                          const float* __restrict__ coef,
                          const float* __restrict__ maxl,
                          float* __restrict__ dss,
                          float* __restrict__ nss,
                          float* __restrict__ loss,
                          int N, int D, int total)
{
    const int DD = D * D;
    int base = blockIdx.x * (TPB * PPT) + threadIdx.x;

    int   t[PPT];
    bool  valid[PPT];
    float fx[PPT], fy[PPT], fz[PPT];
    const float* gp[PPT];
    float c[PPT][8];

    // Phase 1: address + fraction setup for both points
    #pragma unroll
    for (int p = 0; p < PPT; p++) {
        t[p] = base + p * TPB;
        valid[p] = t[p] < total;
        int tt = valid[p] ? t[p] : 0;
        int b = tt / N;
        int n = tt - b * N;

        float px = pss[((size_t)b * 3 + 0) * N + n];
        float py = pss[((size_t)b * 3 + 1) * N + n];
        float pz = pss[((size_t)b * 3 + 2) * N + n];

        float fxf = fmaxf(fminf((px - first[b*3+0]) * coef[b*3+0], maxl[b*3+0]), 0.0f);
        float fyf = fmaxf(fminf((py - first[b*3+1]) * coef[b*3+1], maxl[b*3+1]), 0.0f);
        float fzf = fmaxf(fminf((pz - first[b*3+2]) * coef[b*3+2], maxl[b*3+2]), 0.0f);

        float bx = floorf(fxf), by = floorf(fyf), bz = floorf(fzf);
        fx[p] = fxf - bx;  fy[p] = fyf - by;  fz[p] = fzf - bz;

        gp[p] = grid + (size_t)b * D * DD
                     + (size_t)(int)bx * DD
                     + (size_t)(int)by * D
                     + (size_t)(int)bz;
    }

    // Phase 2: issue all 16 gathers back-to-back (max MLP)
    #pragma unroll
    for (int p = 0; p < PPT; p++) {
        c[p][0] = __ldg(gp[p]);
        c[p][1] = __ldg(gp[p] + 1);
        c[p][2] = __ldg(gp[p] + D);
        c[p][3] = __ldg(gp[p] + D + 1);
        c[p][4] = __ldg(gp[p] + DD);
        c[p][5] = __ldg(gp[p] + DD + 1);
        c[p][6] = __ldg(gp[p] + DD + D);
        c[p][7] = __ldg(gp[p] + DD + D + 1);
    }

    // Phase 3: math + stores
    float my_loss = 0.0f;
    #pragma unroll
    for (int p = 0; p < PPT; p++) {
        float c000 = c[p][0], c001 = c[p][1], c010 = c[p][2], c011 = c[p][3];
        float c100 = c[p][4], c101 = c[p][5], c110 = c[p][6], c111 = c[p][7];
        float Fx = fx[p], Fy = fy[p], Fz = fz[p];
        float wx0 = 1.0f - Fx, wx1 = Fx;
        float wy0 = 1.0f - Fy, wy1 = Fy;
        float wz0 = 1.0f - Fz, wz1 = Fz;

        // trilinear value
        float a00 = fmaf(Fz, c001 - c000, c000);
        float a01 = fmaf(Fz, c011 - c010, c010);
        float a10 = fmaf(Fz, c101 - c100, c100);
        float a11 = fmaf(Fz, c111 - c110, c110);
        float b0  = fmaf(Fy, a01 - a00, a00);
        float b1  = fmaf(Fy, a11 - a10, a10);
        float d   = fmaf(Fx, b1 - b0, b0);

        // finite-difference normals
        float nz = ((c001-c000) * wy0 + (c011-c010) * wy1) * wx0
                 + ((c101-c100) * wy0 + (c111-c110) * wy1) * wx1;
        float ny = ((c010-c000) * wz0 + (c011-c001) * wz1) * wx0
                 + ((c110-c100) * wz0 + (c111-c101) * wz1) * wx1;
        float nx = ((c100-c000) * wz0 + (c101-c001) * wz1) * wy0
                 + ((c110-c010) * wz0 + (c111-c011) * wz1) * wy1;

        float norm = sqrtf(nx*nx + ny*ny + nz*nz);
        float inv  = 1.0f / fmaxf(norm, EPS);

        if (valid[p]) {
            dss[t[p]] = d;
            nss[3 * (size_t)t[p] + 0] = nx * inv;
            nss[3 * (size_t)t[p] + 1] = ny * inv;
            nss[3 * (size_t)t[p] + 2] = nz * inv;
            my_loss += -fminf(d, 0.0f);
        }
    }

    // block reduction of loss
    __shared__ float warp_sums[TPB / 32];
    __shared__ bool  is_last;
    int lane = threadIdx.x & 31;
    int warp = threadIdx.x >> 5;

    #pragma unroll
    for (int off = 16; off > 0; off >>= 1)
        my_loss += __shfl_down_sync(0xFFFFFFFFu, my_loss, off);
    if (lane == 0) warp_sums[warp] = my_loss;
    __syncthreads();

    if (warp == 0) {
        float s = (lane < (TPB >> 5)) ? warp_sums[lane] : 0.0f;
        #pragma unroll
        for (int off = 4; off > 0; off >>= 1)
            s += __shfl_down_sync(0xFFFFFFFFu, s, off);
        if (lane == 0) {
            g_partials[blockIdx.x] = s;
            __threadfence();
            // self-resetting ticket: wraps to 0 when old == gridDim.x-1
            unsigned int ticket = atomicInc(&g_count, gridDim.x - 1);
            is_last = (ticket == gridDim.x - 1);
        }
    }
    __syncthreads();

    // last block to finish sums all partials and writes the scalar loss
    if (is_last) {
        float s = 0.0f;
        for (int i = threadIdx.x; i < (int)gridDim.x; i += TPB)
            s += __ldcg(&g_partials[i]);   // L1-bypass: read L2-visible values

        #pragma unroll
        for (int off = 16; off > 0; off >>= 1)
            s += __shfl_down_sync(0xFFFFFFFFu, s, off);
        if (lane == 0) warp_sums[warp] = s;
        __syncthreads();
        if (warp == 0) {
            float v = (lane < (TPB >> 5)) ? warp_sums[lane] : 0.0f;
            #pragma unroll
            for (int off = 4; off > 0; off >>= 1)
                v += __shfl_down_sync(0xFFFFFFFFu, v, off);
            if (lane == 0) *loss = v;
        }
    }
}

extern "C" void kernel_launch(void* const* d_in, const int* in_sizes, int n_in,
                              void* d_out, int out_size)
{
    const float* pss   = (const float*)d_in[0];
    const float* grid  = (const float*)d_in[1];
    const float* first = (const float*)d_in[2];
    const float* coef  = (const float*)d_in[3];
    const float* maxl  = (const float*)d_in[4];

    int B = in_sizes[2] / 3;
    int N = in_sizes[0] / (3 * B);
    long per_b = (long)in_sizes[1] / B;
    int D = 1;
    while ((long)(D + 1) * (D + 1) * (D + 1) <= per_b) D++;

    int total = B * N;

    float* dss  = (float*)d_out;
    float* nss  = dss + (size_t)total;
    float* loss = dss + (size_t)4 * total;

    int pts_per_block = TPB * PPT;
    int blocks = (total + pts_per_block - 1) / pts_per_block;

    sdf_trilinear_kernel<<<blocks, TPB>>>(pss, grid, first, coef, maxl,
                                          dss, nss, loss, N, D, total);
}

// round 6
// speedup vs baseline: 1.0585x; 1.0585x over previous
#include <cuda_runtime.h>
#include <cuda_bf16.h>

// Distance_74406013436418: trilinear SDF interpolation + finite-difference
// normals + hinge loss.
//
// Output (float32): [dss B*N | nss B*N*3 | loss 1]
//
// R6: R3 body (1 point/thread, max occupancy — SM-wide MLP is the lever, not
// per-thread MLP) + single-kernel graph via self-resetting ticket reduction
// (removes the serialized 4B memset node that cost ~3.9us in R3).

#define EPS 1e-5f
#define TPB 256

// per-block loss partials (fully overwritten each launch -> deterministic)
__device__ float g_partials[8192];
// ticket counter: atomicInc with limit gridDim-1 wraps to 0 -> self-resetting across replays
__device__ unsigned int g_count = 0;

__global__ __launch_bounds__(TPB)
void sdf_trilinear_kernel(const float* __restrict__ pss,
                          const float* __restrict__ grid,
                          const float* __restrict__ first,
                          const float* __restrict__ coef,
                          const float* __restrict__ maxl,
                          float* __restrict__ dss,
                          float* __restrict__ nss,
                          float* __restrict__ loss,
                          int N, int D, int total)
{
    int t = blockIdx.x * TPB + threadIdx.x;

    float my_loss = 0.0f;

    if (t < total) {
        int b = t / N;
        int n = t - b * N;

        // point coords (coalesced: stride-1 in n)
        float px = pss[((size_t)b * 3 + 0) * N + n];
        float py = pss[((size_t)b * 3 + 1) * N + n];
        float pz = pss[((size_t)b * 3 + 2) * N + n];

        float f0x = first[b * 3 + 0], f0y = first[b * 3 + 1], f0z = first[b * 3 + 2];
        float cx  = coef[b * 3 + 0],  cy  = coef[b * 3 + 1],  cz  = coef[b * 3 + 2];
        float mx  = maxl[b * 3 + 0],  my  = maxl[b * 3 + 1],  mz  = maxl[b * 3 + 2];

        float fx_full = fmaxf(fminf((px - f0x) * cx, mx), 0.0f);
        float fy_full = fmaxf(fminf((py - f0y) * cy, my), 0.0f);
        float fz_full = fmaxf(fminf((pz - f0z) * cz, mz), 0.0f);

        float bx = floorf(fx_full);
        float by = floorf(fy_full);
        float bz = floorf(fz_full);
        float fx = fx_full - bx;
        float fy = fy_full - by;
        float fz = fz_full - bz;

        int ix = (int)bx, iy = (int)by, iz = (int)bz;
        const int DD = D * D;

        const float* g = grid + (size_t)b * D * DD
                              + (size_t)ix * DD
                              + (size_t)iy * D
                              + (size_t)iz;

        // 8 gathers issued back-to-back (all independent)
        float c000 = __ldg(g);
        float c001 = __ldg(g + 1);
        float c010 = __ldg(g + D);
        float c011 = __ldg(g + D + 1);
        float c100 = __ldg(g + DD);
        float c101 = __ldg(g + DD + 1);
        float c110 = __ldg(g + DD + D);
        float c111 = __ldg(g + DD + D + 1);

        float wx0 = 1.0f - fx, wx1 = fx;
        float wy0 = 1.0f - fy, wy1 = fy;
        float wz0 = 1.0f - fz, wz1 = fz;

        // trilinear value (lerp chain: z, then y, then x)
        float a00 = fmaf(fz, c001 - c000, c000);
        float a01 = fmaf(fz, c011 - c010, c010);
        float a10 = fmaf(fz, c101 - c100, c100);
        float a11 = fmaf(fz, c111 - c110, c110);
        float b0  = fmaf(fy, a01 - a00, a00);
        float b1  = fmaf(fy, a11 - a10, a10);
        float d   = fmaf(fx, b1 - b0, b0);

        // finite-difference normals
        float nz = ((c001-c000) * wy0 + (c011-c010) * wy1) * wx0
                 + ((c101-c100) * wy0 + (c111-c110) * wy1) * wx1;
        float ny = ((c010-c000) * wz0 + (c011-c001) * wz1) * wx0
                 + ((c110-c100) * wz0 + (c111-c101) * wz1) * wx1;
        float nx = ((c100-c000) * wz0 + (c101-c001) * wz1) * wy0
                 + ((c110-c010) * wz0 + (c111-c011) * wz1) * wy1;

        float norm = sqrtf(nx * nx + ny * ny + nz * nz);
        float inv  = 1.0f / fmaxf(norm, EPS);

        dss[t] = d;
        nss[3 * (size_t)t + 0] = nx * inv;
        nss[3 * (size_t)t + 1] = ny * inv;
        nss[3 * (size_t)t + 2] = nz * inv;

        my_loss = -fminf(d, 0.0f);
    }

    // block reduction of loss
    __shared__ float warp_sums[TPB / 32];
    __shared__ bool  is_last;
    int lane = threadIdx.x & 31;
    int warp = threadIdx.x >> 5;

    #pragma unroll
    for (int off = 16; off > 0; off >>= 1)
        my_loss += __shfl_down_sync(0xFFFFFFFFu, my_loss, off);
    if (lane == 0) warp_sums[warp] = my_loss;
    __syncthreads();

    if (warp == 0) {
        float s = (lane < (TPB >> 5)) ? warp_sums[lane] : 0.0f;
        #pragma unroll
        for (int off = 4; off > 0; off >>= 1)
            s += __shfl_down_sync(0xFFFFFFFFu, s, off);
        if (lane == 0) {
            g_partials[blockIdx.x] = s;
            __threadfence();
            // self-resetting ticket: wraps to 0 when old == gridDim.x-1
            unsigned int ticket = atomicInc(&g_count, gridDim.x - 1);
            is_last = (ticket == gridDim.x - 1);
        }
    }
    __syncthreads();

    // last block to finish sums all partials and writes the scalar loss
    if (is_last) {
        float s = 0.0f;
        for (int i = threadIdx.x; i < (int)gridDim.x; i += TPB)
            s += __ldcg(&g_partials[i]);   // L1-bypass: read L2-visible values

        #pragma unroll
        for (int off = 16; off > 0; off >>= 1)
            s += __shfl_down_sync(0xFFFFFFFFu, s, off);
        if (lane == 0) warp_sums[warp] = s;
        __syncthreads();
        if (warp == 0) {
            float v = (lane < (TPB >> 5)) ? warp_sums[lane] : 0.0f;
            #pragma unroll
            for (int off = 4; off > 0; off >>= 1)
                v += __shfl_down_sync(0xFFFFFFFFu, v, off);
            if (lane == 0) *loss = v;
        }
    }
}

extern "C" void kernel_launch(void* const* d_in, const int* in_sizes, int n_in,
                              void* d_out, int out_size)
{
    const float* pss   = (const float*)d_in[0];
    const float* grid  = (const float*)d_in[1];
    const float* first = (const float*)d_in[2];
    const float* coef  = (const float*)d_in[3];
    const float* maxl  = (const float*)d_in[4];

    int B = in_sizes[2] / 3;
    int N = in_sizes[0] / (3 * B);
    long per_b = (long)in_sizes[1] / B;
    int D = 1;
    while ((long)(D + 1) * (D + 1) * (D + 1) <= per_b) D++;

    int total = B * N;

    float* dss  = (float*)d_out;
    float* nss  = dss + (size_t)total;
    float* loss = dss + (size_t)4 * total;

    int blocks = (total + TPB - 1) / TPB;
    sdf_trilinear_kernel<<<blocks, TPB>>>(pss, grid, first, coef, maxl,
                                          dss, nss, loss, N, D, total);
}